// round 16
// baseline (speedup 1.0000x reference)
#include <cuda_runtime.h>
#include <cuda_bf16.h>
#include <stdint.h>
#include <math.h>
#define NMAX 50000
#define EMAX 500000
typedef unsigned long long ull;
typedef unsigned int u32;
#define H2SM 104448   // hmma2: 4-chunk X (81920) + B (20480) + red pad
#define H5SM 66560    // hmma512: A 2x20480 | B 2x10240 | red 4096

__device__ float g_t [(size_t)256*EMAX];
__device__ float g_xe[(size_t)128*EMAX];
__device__ float g_sN[(size_t)384*NMAX];
__device__ float g_yAT[(size_t)256*NMAX];
__device__ float g_k1n[32*128];
__device__ float g_k2n[128*128];
__device__ float g_k1e[32*128];
__device__ __nv_bfloat16 g_bhN1[4*256*384], g_blN1[4*256*384];
__device__ __nv_bfloat16 g_bhN2[4*128*256], g_blN2[4*128*256];
__device__ __nv_bfloat16 g_bhEa[4*256*128], g_blEa[4*256*128];
__device__ __nv_bfloat16 g_bhE1[4*256*128], g_blE1[4*256*128];
__device__ __nv_bfloat16 g_bhE2[4*128*256], g_blE2[4*128*256];
__device__ __nv_bfloat16 g_bhOE[128*128],   g_blOE[128*128];
__device__ __nv_bfloat16 g_bhKO[128*128],   g_blKO[128*128];
__device__ double g_acc[20];

__device__ __forceinline__ ull dup2(float v){ ull r; asm("mov.b64 %0,{%1,%1};":"=l"(r):"f"(v)); return r; }
__device__ __forceinline__ void ffma2(ull&d, ull a, ull b){ asm("fma.rn.f32x2 %0,%1,%2,%0;":"+l"(d):"l"(a),"l"(b)); }
__device__ __forceinline__ float2 f2of(ull u){ union{ull u; float2 f;} c; c.u=u; return c.f; }
__device__ __forceinline__ u32 smem_u32(const void*p){ u32 a; asm("{.reg .u64 t; cvta.to.shared.u64 t,%1; cvt.u32.u64 %0,t;}":"=r"(a):"l"(p)); return a; }
#define LDM4(r,a) asm volatile("ldmatrix.sync.aligned.m8n8.x4.shared.b16 {%0,%1,%2,%3},[%4];" \
    :"=r"((r)[0]),"=r"((r)[1]),"=r"((r)[2]),"=r"((r)[3]):"r"(a))
#define MMA(dd,a,b0,b1) asm volatile("mma.sync.aligned.m16n8k16.row.col.f32.bf16.bf16.f32 " \
    "{%0,%1,%2,%3},{%4,%5,%6,%7},{%8,%9},{%0,%1,%2,%3};" \
    :"+f"((dd)[0]),"+f"((dd)[1]),"+f"((dd)[2]),"+f"((dd)[3]) \
    :"r"((a)[0]),"r"((a)[1]),"r"((a)[2]),"r"((a)[3]),"r"(b0),"r"(b1))
#define REDV2(p,x0,x1) asm volatile("red.global.add.v2.f32 [%0], {%1, %2};" :: "l"(p), "f"(x0), "f"(x1) : "memory")

__device__ __forceinline__ void bsplit(float w, __nv_bfloat16& h, __nv_bfloat16& l){
    h = __float2bfloat16(w); l = __float2bfloat16(w - __bfloat162float(h));
}
__device__ __forceinline__ void bsplit8(const float* xv, uint4& uh, uint4& ul){
    __nv_bfloat162 h[4], l[4];
    #pragma unroll
    for (int p = 0; p < 4; p++) {
        float2 x2 = make_float2(xv[2*p], xv[2*p+1]);
        h[p] = __float22bfloat162_rn(x2);
        float2 hf = __bfloat1622float2(h[p]);
        l[p] = __float22bfloat162_rn(make_float2(x2.x - hf.x, x2.y - hf.y));
    }
    uh = *(uint4*)h; ul = *(uint4*)l;
}

__global__ void prep_kernelA(const float* __restrict__ KE1, const float* __restrict__ KN1,
                             const float* __restrict__ KE2, const float* __restrict__ KN2)
{
    int idx = blockIdx.x*blockDim.x + threadIdx.x;
    if (idx >= 4*256*384) return;
    int l = idx / (256*384), r = idx % (256*384);
    int o = r / 384, k = r % 384;
    {
        const float* n = KN1 + ((size_t)(l*256 + o))*384;
        int kk = k & 127, reg = k >> 7;
        float a = n[kk], b = n[128+kk];
        float w = (reg == 0) ? 0.5f*a + b : ((reg == 1) ? 0.5f*a - b : n[256+kk]);
        bsplit(w, g_bhN1[(size_t)(l*256+o)*384 + k], g_blN1[(size_t)(l*256+o)*384 + k]);
    }
    if (k < 128) {
        const float* e = KE1 + ((size_t)(l*256 + o))*384;
        int d = (l*256 + o)*128 + k;
        bsplit(e[k] + e[128+k], g_bhEa[d], g_blEa[d]);
        bsplit(e[256+k],        g_bhE1[d], g_blE1[d]);
    }
    if (o < 128 && k < 256) {
        int d = (l*128 + o)*256 + k;
        bsplit(KE2[(size_t)(l*128+o)*256 + k], g_bhE2[d], g_blE2[d]);
        bsplit(KN2[(size_t)(l*128+o)*256 + k], g_bhN2[d], g_blN2[d]);
    }
}
__global__ void prep_kernelB(const float* __restrict__ K1No, const float* __restrict__ K2No,
                             const float* __restrict__ K1Eo, const float* __restrict__ K2Eo,
                             const float* __restrict__ KNout)
{
    int idx = blockIdx.x*blockDim.x + threadIdx.x;
    if (idx >= 128*128) return;
    int o = idx&127, k = idx>>7;
    if (k < 32) { g_k1n[k*128+o] = K1No[o*32+k]; g_k1e[k*128+o] = K1Eo[o*32+k]; }
    g_k2n[k*128+o] = K2No[o*128+k];
    bsplit(K2Eo[o*128+k], g_bhOE[o*128+k], g_blOE[o*128+k]);
    bsplit((o < 64) ? KNout[o*128+k] : 0.f, g_bhKO[o*128+k], g_blKO[o*128+k]);
}

__global__ void zeroS(float* s, int N)
{
    int i = blockIdx.x*blockDim.x + threadIdx.x;
    if (i >= N*64) return;
    int n = i >> 6, c = (i & 63)*4;
    *(float4*)(s + (size_t)n*384 + c) = make_float4(0.f,0.f,0.f,0.f);
}

__global__ void transposeNC(const float* __restrict__ src, float* __restrict__ dst,
                            int M, int ldS, int rows)
{
    __shared__ float tl[32][33];
    int m0 = blockIdx.x*32, c0 = blockIdx.y*32;
    int tx = threadIdx.x, ty = threadIdx.y;
    #pragma unroll
    for (int i = 0; i < 32; i += 8) {
        int m = m0 + ty + i;
        tl[ty+i][tx] = (m < M) ? src[(size_t)m*ldS + c0 + tx] : 0.f;
    }
    __syncthreads();
    #pragma unroll
    for (int i = 0; i < 32; i += 8) {
        int m = m0 + tx, c = c0 + ty + i;
        if (m < M && c < rows) dst[(size_t)c*M + m] = tl[tx][ty+i];
    }
}

// ---------- generic HMMA GEMM: 512 threads, M=256 tile (W staged once per 256 edges) ----------
__global__ void __launch_bounds__(512, 2)
hmma_kernel(int E, int K, int ldX, int ldY,
            const __nv_bfloat16* __restrict__ Whi, const __nv_bfloat16* __restrict__ Wlo,
            const float* __restrict__ X,
            const double* __restrict__ normAcc, double cntInv, double* __restrict__ statAcc,
            float* __restrict__ Y, int epi,
            float* __restrict__ sc, int ldS,
            const int* __restrict__ iI, const int* __restrict__ jI)
{
    extern __shared__ __align__(16) char dsm[];
    const int A_H = 0, A_L = 20480, B_H = 40960, B_L = 51200;
    const u32 sb = smem_u32(dsm);

    const int tid = threadIdx.x, warp = tid>>5, lane = tid&31;
    const int m0 = blockIdx.x*256;
    const int oB = blockIdx.y*128;
    const int wm = warp>>1, wn = warp&1;          // wm 0..7, wn 0..1
    const int ce = tid & 255, cg = tid >> 8;      // X staging: edge, k-half
    const int wrow = tid & 127, wq = tid >> 7;    // W staging: out row, k-quarter
    const bool cev = (m0 + ce) < E;

    const __nv_bfloat16* WhB = Whi + (size_t)(oB + wrow)*K;
    const __nv_bfloat16* WlB = Wlo + (size_t)(oB + wrow)*K;

    float inv = 0.f, mi = 0.f;
    const bool dn = (normAcc != nullptr);
    if (dn) {
        double mu = normAcc[0]*cntInv, va = normAcc[1]*cntInv - mu*mu;
        inv = (float)rsqrt(va + 1e-5);
        mi  = (float)mu * inv;
    }

    float d[2][8][4];
    #pragma unroll
    for (int a = 0; a < 2; a++)
        #pragma unroll
        for (int b = 0; b < 8; b++)
            #pragma unroll
            for (int c = 0; c < 4; c++) d[a][b][c] = 0.f;

    const float* xrow = X + (size_t)(m0 + ce)*ldX + cg*16;

    const int C = K >> 5;
    for (int c = 0; c < C; c++) {
        const int k0 = c*32;
        __syncthreads();
        // stage X: 16 contiguous floats/thread
        #pragma unroll
        for (int h = 0; h < 2; h++) {
            float xv[8];
            if (cev) {
                *(float4*)&xv[0] = *(const float4*)(xrow + k0 + h*8);
                *(float4*)&xv[4] = *(const float4*)(xrow + k0 + h*8 + 4);
            } else {
                #pragma unroll
                for (int i = 0; i < 8; i++) xv[i] = 0.f;
            }
            if (dn) {
                #pragma unroll
                for (int i = 0; i < 8; i++) xv[i] = fmaxf(fmaf(xv[i], inv, -mi), 0.f);
            }
            uint4 uh, ul;
            bsplit8(xv, uh, ul);
            int kof = cg*16 + h*8;
            *(uint4*)(dsm + A_H + ce*80 + kof*2) = uh;
            *(uint4*)(dsm + A_L + ce*80 + kof*2) = ul;
        }
        // stage W: 1 uint4/plane/thread (halved vs 256-thread version)
        {
            int kof = wq*8;
            *(uint4*)(dsm + B_H + wrow*80 + kof*2) = *(const uint4*)(WhB + k0 + kof);
            *(uint4*)(dsm + B_L + wrow*80 + kof*2) = *(const uint4*)(WlB + k0 + kof);
        }
        __syncthreads();
        #pragma unroll
        for (int kk = 0; kk < 32; kk += 16) {
            u32 ah[2][4], al[2][4];
            #pragma unroll
            for (int mt = 0; mt < 2; mt++) {
                u32 ra = sb + (u32)((wm*32 + mt*16 + (lane&15))*80 + (kk + ((lane>>4)<<3))*2);
                LDM4(ah[mt], A_H + ra);
                LDM4(al[mt], A_L + ra);
            }
            #pragma unroll
            for (int np = 0; np < 4; np++) {
                u32 rb = sb + (u32)((wn*64 + np*16 + (lane&7) + ((lane>>4)<<3))*80 + (kk + ((lane>>3)&1)*8)*2);
                u32 bh[4], bl[4];
                LDM4(bh, B_H + rb);
                LDM4(bl, B_L + rb);
                #pragma unroll
                for (int mt = 0; mt < 2; mt++) {
                    MMA(d[mt][np*2],   ah[mt], bh[0], bh[1]);
                    MMA(d[mt][np*2],   ah[mt], bl[0], bl[1]);
                    MMA(d[mt][np*2],   al[mt], bh[0], bh[1]);
                    MMA(d[mt][np*2+1], ah[mt], bh[2], bh[3]);
                    MMA(d[mt][np*2+1], ah[mt], bl[2], bl[3]);
                    MMA(d[mt][np*2+1], al[mt], bh[2], bh[3]);
                }
            }
        }
    }

    const int quad = lane>>2, tc = (lane&3)*2;
    float s = 0.f, q = 0.f;
    #pragma unroll
    for (int mt = 0; mt < 2; mt++) {
        #pragma unroll
        for (int hf = 0; hf < 2; hf++) {
            int e = m0 + wm*32 + mt*16 + quad + hf*8;
            if (e >= E) continue;
            float *ip = nullptr, *jp = nullptr;
            if (epi == 2) {
                ip = sc + (size_t)iI[e]*ldS;
                jp = sc + (size_t)jI[e]*ldS + 128;
            }
            float* yrow = Y + (size_t)e*ldY + oB;
            #pragma unroll
            for (int nt = 0; nt < 8; nt++) {
                int oL = wn*64 + nt*8 + tc;
                float x0 = d[mt][nt][hf*2+0];
                float x1 = d[mt][nt][hf*2+1];
                if (epi == 0) {
                    *(float2*)(yrow + oL) = make_float2(x0, x1);
                    s += x0 + x1; q += x0*x0 + x1*x1;
                } else {
                    float2 old = *(float2*)(yrow + oL);
                    old.x += 0.1f*x0; old.y += 0.1f*x1;
                    *(float2*)(yrow + oL) = old;
                    if (epi == 2) {
                        REDV2(ip + oL, x0, x1);
                        REDV2(jp + oL, x0, x1);
                    }
                }
            }
        }
    }
    if (statAcc) {
        float* rs = (float*)(dsm + 61440); float* rq = rs + 512;
        __syncthreads();
        rs[tid] = s; rq[tid] = q;
        __syncthreads();
        for (int st = 256; st > 0; st >>= 1) {
            if (tid < st) { rs[tid] += rs[tid+st]; rq[tid] += rq[tid+st]; }
            __syncthreads();
        }
        if (tid == 0) { atomicAdd(statAcc, (double)rs[0]); atomicAdd(statAcc+1, (double)rq[0]); }
    }
}

// ---------- two-pass HMMA for K=128, O=256 (X staged once), float2 gather ----------
__global__ void __launch_bounds__(256, 2)
hmma2_kernel(int E, int ldX,
             const __nv_bfloat16* __restrict__ Whi, const __nv_bfloat16* __restrict__ Wlo,
             const float* __restrict__ X,
             const float* __restrict__ gInit, const int* __restrict__ g0,
             double* __restrict__ statAcc,
             float* __restrict__ Y)
{
    extern __shared__ __align__(16) char dsm[];
    const int B_H = 81920, B_L = 92160;
    const u32 sb = smem_u32(dsm);

    const int tid = threadIdx.x, warp = tid>>5, lane = tid&31;
    const int m0 = blockIdx.x*128;
    const int wm = warp>>1, wn = warp&1;
    const int ce = tid & 127, cg = tid >> 7;
    const bool cev = (m0 + ce) < E;

    const float* xrow = X + (size_t)(m0 + ce)*ldX + cg*16;

    #pragma unroll
    for (int c = 0; c < 4; c++) {
        const int k0 = c*32;
        char* ab = dsm + c*20480;
        #pragma unroll
        for (int h = 0; h < 2; h++) {
            float xv[8];
            if (cev) {
                *(float4*)&xv[0] = *(const float4*)(xrow + k0 + h*8);
                *(float4*)&xv[4] = *(const float4*)(xrow + k0 + h*8 + 4);
            } else {
                #pragma unroll
                for (int i = 0; i < 8; i++) xv[i] = 0.f;
            }
            uint4 uh, ul;
            bsplit8(xv, uh, ul);
            int kof = cg*16 + h*8;
            *(uint4*)(ab +         ce*80 + kof*2) = uh;
            *(uint4*)(ab + 10240 + ce*80 + kof*2) = ul;
        }
    }

    const int quad = lane>>2, tc = (lane&3)*2;
    float s = 0.f, q = 0.f;

    for (int oh = 0; oh < 2; oh++) {
        const int oB = oh*128;
        const __nv_bfloat16* WhB = Whi + (size_t)(oB + ce)*128;
        const __nv_bfloat16* WlB = Wlo + (size_t)(oB + ce)*128;

        float d[2][8][4];
        #pragma unroll
        for (int a = 0; a < 2; a++)
            #pragma unroll
            for (int b = 0; b < 8; b++)
                #pragma unroll
                for (int c = 0; c < 4; c++) d[a][b][c] = 0.f;

        for (int c = 0; c < 4; c++) {
            const int k0 = c*32;
            __syncthreads();
            #pragma unroll
            for (int h = 0; h < 2; h++) {
                int kof = (cg + h*2)*8;
                *(uint4*)(dsm + B_H + ce*80 + kof*2) = *(const uint4*)(WhB + k0 + kof);
                *(uint4*)(dsm + B_L + ce*80 + kof*2) = *(const uint4*)(WlB + k0 + kof);
            }
            __syncthreads();
            const u32 abs0 = sb + (u32)(c*20480);
            #pragma unroll
            for (int kk = 0; kk < 32; kk += 16) {
                u32 ah[2][4], al[2][4];
                #pragma unroll
                for (int mt = 0; mt < 2; mt++) {
                    u32 ra = (u32)((wm*32 + mt*16 + (lane&15))*80 + (kk + ((lane>>4)<<3))*2);
                    LDM4(ah[mt], abs0 + ra);
                    LDM4(al[mt], abs0 + 10240 + ra);
                }
                #pragma unroll
                for (int np = 0; np < 4; np++) {
                    u32 rb = sb + (u32)((wn*64 + np*16 + (lane&7) + ((lane>>4)<<3))*80 + (kk + ((lane>>3)&1)*8)*2);
                    u32 bh[4], bl[4];
                    LDM4(bh, B_H + rb);
                    LDM4(bl, B_L + rb);
                    #pragma unroll
                    for (int mt = 0; mt < 2; mt++) {
                        MMA(d[mt][np*2],   ah[mt], bh[0], bh[1]);
                        MMA(d[mt][np*2],   ah[mt], bl[0], bl[1]);
                        MMA(d[mt][np*2],   al[mt], bh[0], bh[1]);
                        MMA(d[mt][np*2+1], ah[mt], bh[2], bh[3]);
                        MMA(d[mt][np*2+1], ah[mt], bl[2], bl[3]);
                        MMA(d[mt][np*2+1], al[mt], bh[2], bh[3]);
                    }
                }
            }
        }

        #pragma unroll
        for (int mt = 0; mt < 2; mt++) {
            #pragma unroll
            for (int hf = 0; hf < 2; hf++) {
                int e = m0 + wm*32 + mt*16 + quad + hf*8;
                if (e >= E) continue;
                const float* gp = nullptr;
                if (gInit) gp = gInit + (size_t)g0[e]*256 + oB;
                float* yrow = Y + (size_t)e*256 + oB;
                #pragma unroll
                for (int nt = 0; nt < 8; nt++) {
                    int oL = wn*64 + nt*8 + tc;
                    float x0 = d[mt][nt][hf*2+0];
                    float x1 = d[mt][nt][hf*2+1];
                    if (gp) {
                        float2 g2 = *(const float2*)(gp + oL);
                        x0 += g2.x; x1 += g2.y;
                    }
                    *(float2*)(yrow + oL) = make_float2(x0, x1);
                    s += x0 + x1; q += x0*x0 + x1*x1;
                }
            }
        }
    }

    if (statAcc) {
        float* rs = (float*)(dsm + 102400); float* rq = rs + 256;
        __syncthreads();
        rs[tid] = s; rq[tid] = q;
        __syncthreads();
        for (int st = 128; st > 0; st >>= 1) {
            if (tid < st) { rs[tid] += rs[tid+st]; rq[tid] += rq[tid+st]; }
            __syncthreads();
        }
        if (tid == 0) { atomicAdd(statAcc, (double)rs[0]); atomicAdd(statAcc+1, (double)rq[0]); }
    }
}

// ---------- SIMT f32x2 GEMM (opening GEMMs only) ----------
__global__ void __launch_bounds__(256, 2)
mm4_kernel(int M, int Oact, int ldY3,
           const float* __restrict__ W0, const float* __restrict__ X0, int K0, int ld0, int ldW0,
           const double* __restrict__ normAcc, double cntInv, double* __restrict__ statAcc,
           float* __restrict__ Y, int epi)
{
    __shared__ __align__(16) ull   Wd[2][8][132];
    __shared__ __align__(16) float Xs[2][8][132];
    const int tid = threadIdx.x, m0 = blockIdx.x*128, wb = blockIdx.y*128;
    const int lane = tid&31, warp = tid>>5;
    const int rbase = (warp>>2)*64 + (lane>>2)*4;
    const int cbase = (warp&3)*32 + (lane&3)*4;
    const int kkS = tid>>5, mfS = (tid&31)*4;

    float mean = 0.f, inv = 0.f;
    const bool dn = (normAcc != nullptr);
    if (dn) {
        double mu = normAcc[0]*cntInv, va = normAcc[1]*cntInv - mu*mu;
        mean = (float)mu; inv = (float)rsqrt(va + 1e-5);
    }
    ull acc[8][4];
    #pragma unroll
    for (int r = 0; r < 8; r++) { acc[r][0]=acc[r][1]=acc[r][2]=acc[r][3]=0ull; }

    const int totT = K0 >> 3;
    auto ldg = [&](int t, float4& wv, float4& xv) {
        int k0 = t*8;
        wv = *(const float4*)(W0 + (size_t)(k0+kkS)*ldW0 + wb + mfS);
        int m = m0 + mfS;
        if (m < M) {
            float4 v = *(const float4*)(X0 + (size_t)(k0+kkS)*ld0 + m);
            if (dn) {
                v.x = fmaxf((v.x-mean)*inv, 0.f); v.y = fmaxf((v.y-mean)*inv, 0.f);
                v.z = fmaxf((v.z-mean)*inv, 0.f); v.w = fmaxf((v.w-mean)*inv, 0.f);
            }
            xv = v;
        } else xv = make_float4(0.f,0.f,0.f,0.f);
    };
    auto sts = [&](int b, const float4& wv, const float4& xv) {
        ull* wr = &Wd[b][kkS][mfS];
        wr[0]=dup2(wv.x); wr[1]=dup2(wv.y); wr[2]=dup2(wv.z); wr[3]=dup2(wv.w);
        *(float4*)&Xs[b][kkS][mfS] = xv;
    };
    { float4 wv, xv; ldg(0, wv, xv); sts(0, wv, xv); }
    __syncthreads();
    float4 wpv, xpv;
    for (int t = 0; t < totT; t++) {
        const int cur = t&1; const bool more = (t+1 < totT);
        if (more) ldg(t+1, wpv, xpv);
        #pragma unroll
        for (int kk = 0; kk < 8; kk++) {
            ulonglong2 w01 = *(const ulonglong2*)&Wd[cur][kk][rbase];
            ulonglong2 w23 = *(const ulonglong2*)&Wd[cur][kk][rbase+2];
            ulonglong2 w45 = *(const ulonglong2*)&Wd[cur][kk][rbase+32];
            ulonglong2 w67 = *(const ulonglong2*)&Wd[cur][kk][rbase+34];
            ulonglong2 xa = *(const ulonglong2*)&Xs[cur][kk][cbase];
            ulonglong2 xb = *(const ulonglong2*)&Xs[cur][kk][cbase+16];
            ffma2(acc[0][0],w01.x,xa.x); ffma2(acc[0][1],w01.x,xa.y); ffma2(acc[0][2],w01.x,xb.x); ffma2(acc[0][3],w01.x,xb.y);
            ffma2(acc[1][0],w01.y,xa.x); ffma2(acc[1][1],w01.y,xa.y); ffma2(acc[1][2],w01.y,xb.x); ffma2(acc[1][3],w01.y,xb.y);
            ffma2(acc[2][0],w23.x,xa.x); ffma2(acc[2][1],w23.x,xa.y); ffma2(acc[2][2],w23.x,xb.x); ffma2(acc[2][3],w23.x,xb.y);
            ffma2(acc[3][0],w23.y,xa.x); ffma2(acc[3][1],w23.y,xa.y); ffma2(acc[3][2],w23.y,xb.x); ffma2(acc[3][3],w23.y,xb.y);
            ffma2(acc[4][0],w45.x,xa.x); ffma2(acc[4][1],w45.x,xa.y); ffma2(acc[4][2],w45.x,xb.x); ffma2(acc[4][3],w45.x,xb.y);
            ffma2(acc[5][0],w45.y,xa.x); ffma2(acc[5][1],w45.y,xa.y); ffma2(acc[5][2],w45.y,xb.x); ffma2(acc[5][3],w45.y,xb.y);
            ffma2(acc[6][0],w67.x,xa.x); ffma2(acc[6][1],w67.x,xa.y); ffma2(acc[6][2],w67.x,xb.x); ffma2(acc[6][3],w67.x,xb.y);
            ffma2(acc[7][0],w67.y,xa.x); ffma2(acc[7][1],w67.y,xa.y); ffma2(acc[7][2],w67.y,xb.x); ffma2(acc[7][3],w67.y,xb.y);
        }
        if (more) sts(cur^1, wpv, xpv);
        __syncthreads();
    }
    if (statAcc) {
        float s = 0.f, q = 0.f;
        #pragma unroll
        for (int r = 0; r < 8; r++)
            #pragma unroll
            for (int cg = 0; cg < 2; cg++)
                if (m0 + cbase + cg*16 < M) {
                    float2 a = f2of(acc[r][cg*2]), b = f2of(acc[r][cg*2+1]);
                    s += a.x+a.y+b.x+b.y; q += a.x*a.x+a.y*a.y+b.x*b.x+b.y*b.y;
                }
        __syncthreads();
        float* rs = (float*)Wd; float* rq = rs + 256;
        rs[tid] = s; rq[tid] = q;
        __syncthreads();
        for (int st = 128; st > 0; st >>= 1) {
            if (tid < st) { rs[tid] += rs[tid+st]; rq[tid] += rq[tid+st]; }
            __syncthreads();
        }
        if (tid == 0) { atomicAdd(statAcc,(double)rs[0]); atomicAdd(statAcc+1,(double)rq[0]); }
    }
    if (epi == 3) {
        #pragma unroll
        for (int j = 0; j < 4; j++)
            #pragma unroll
            for (int h = 0; h < 2; h++) {
                int c = m0 + cbase + (j>>1)*16 + (j&1)*2 + h;
                if (c >= M) continue;
                float4 v0, v1;
                if (h == 0) {
                    v0 = make_float4(f2of(acc[0][j]).x, f2of(acc[1][j]).x, f2of(acc[2][j]).x, f2of(acc[3][j]).x);
                    v1 = make_float4(f2of(acc[4][j]).x, f2of(acc[5][j]).x, f2of(acc[6][j]).x, f2of(acc[7][j]).x);
                } else {
                    v0 = make_float4(f2of(acc[0][j]).y, f2of(acc[1][j]).y, f2of(acc[2][j]).y, f2of(acc[3][j]).y);
                    v1 = make_float4(f2of(acc[4][j]).y, f2of(acc[5][j]).y, f2of(acc[6][j]).y, f2of(acc[7][j]).y);
                }
                float* dst = Y + (size_t)c*ldY3 + wb + rbase;
                *(float4*)dst = v0; *(float4*)(dst+32) = v1;
            }
        return;
    }
    #pragma unroll
    for (int r = 0; r < 8; r++) {
        int o = wb + ((r < 4) ? (rbase + r) : (rbase + 28 + r));
        if (o >= Oact) continue;
        #pragma unroll
        for (int cg = 0; cg < 2; cg++) {
            int c = m0 + cbase + cg*16;
            if (c >= M) continue;
            float2 p0 = f2of(acc[r][cg*2]), p1 = f2of(acc[r][cg*2+1]);
            *(float4*)(Y + (size_t)o*M + c) = make_float4(p0.x, p0.y, p1.x, p1.y);
        }
    }
}

static inline void mm_launch(int M, int ldY3,
    const float* W0, const float* X0, int K0, int ld0, int ldW0,
    const double* nA, double ci, double* sA, float* Y, int epi)
{
    dim3 g((M+127)/128, 1);
    mm4_kernel<<<g, 256>>>(M, 128, ldY3, W0, X0, K0, ld0, ldW0, nA, ci, sA, Y, epi);
}
static inline void hmma_launch(int M, int O, int K, int ldX, int ldY,
    const __nv_bfloat16* Wh, const __nv_bfloat16* Wl, const float* X,
    const double* nA, double ci, double* sA,
    float* Y, int epi, float* sc, int ldS, const int* iI, const int* jI)
{
    dim3 g((M+255)/256, O/128);
    hmma_kernel<<<g, 512, H5SM>>>(M, K, ldX, ldY, Wh, Wl, X, nA, ci, sA, Y, epi, sc, ldS, iI, jI);
}
static inline void hmma2_launch(int M, int ldX,
    const __nv_bfloat16* Wh, const __nv_bfloat16* Wl, const float* X,
    const float* gI, const int* g0, double* sA, float* Y)
{
    hmma2_kernel<<<(M+127)/128, 256, H2SM>>>(M, ldX, Wh, Wl, X, gI, g0, sA, Y);
}

extern "C" void kernel_launch(void* const* d_in, const int* in_sizes, int n_in,
                              void* d_out, int out_size)
{
    if (n_in < 13) return;
    const float* xn_in = (const float*)d_in[0];
    const float* xe_in = (const float*)d_in[1];
    const int* iInd = (const int*)d_in[2];
    const int* jInd = (const int*)d_in[3];
    const float* K1No = (const float*)d_in[4];
    const float* K2No = (const float*)d_in[5];
    const float* K1Eo = (const float*)d_in[6];
    const float* K2Eo = (const float*)d_in[7];
    const float* KNout= (const float*)d_in[8];
    const float* KE1  = (const float*)d_in[9];
    const float* KE2  = (const float*)d_in[10];
    const float* KN1  = (const float*)d_in[11];
    const float* KN2  = (const float*)d_in[12];
    int N = in_sizes[0]/32, E = in_sizes[1]/32;

    cudaFuncSetAttribute(hmma_kernel,  cudaFuncAttributeMaxDynamicSharedMemorySize, H5SM);
    cudaFuncSetAttribute(hmma2_kernel, cudaFuncAttributeMaxDynamicSharedMemorySize, H2SM);

    float *t,*xe,*sN,*yAT,*k1n,*k2n,*k1e;
    __nv_bfloat16 *bhN1,*blN1,*bhN2,*blN2,*bhEa,*blEa,*bhE1,*blE1,*bhE2,*blE2,*bhOE,*blOE,*bhKO,*blKO;
    double* acc;
    cudaGetSymbolAddress((void**)&t,g_t);     cudaGetSymbolAddress((void**)&xe,g_xe);
    cudaGetSymbolAddress((void**)&sN,g_sN);   cudaGetSymbolAddress((void**)&yAT,g_yAT);
    cudaGetSymbolAddress((void**)&k1n,g_k1n); cudaGetSymbolAddress((void**)&k2n,g_k2n);
    cudaGetSymbolAddress((void**)&k1e,g_k1e);
    cudaGetSymbolAddress((void**)&bhN1,g_bhN1); cudaGetSymbolAddress((void**)&blN1,g_blN1);
    cudaGetSymbolAddress((void**)&bhN2,g_bhN2); cudaGetSymbolAddress((void**)&blN2,g_blN2);
    cudaGetSymbolAddress((void**)&bhEa,g_bhEa); cudaGetSymbolAddress((void**)&blEa,g_blEa);
    cudaGetSymbolAddress((void**)&bhE1,g_bhE1); cudaGetSymbolAddress((void**)&blE1,g_blE1);
    cudaGetSymbolAddress((void**)&bhE2,g_bhE2); cudaGetSymbolAddress((void**)&blE2,g_blE2);
    cudaGetSymbolAddress((void**)&bhOE,g_bhOE); cudaGetSymbolAddress((void**)&blOE,g_blOE);
    cudaGetSymbolAddress((void**)&bhKO,g_bhKO); cudaGetSymbolAddress((void**)&blKO,g_blKO);
    cudaGetSymbolAddress((void**)&acc,g_acc);

    float* out = (float*)d_out;
    float* xe_out = out + (size_t)64*N;
    float* xnR = sN + 256;

    cudaMemsetAsync(acc, 0, 20*sizeof(double), 0);
    prep_kernelA<<<(4*256*384+255)/256, 256>>>(KE1, KN1, KE2, KN2);
    prep_kernelB<<<(128*128+255)/256, 256>>>(K1No, K2No, K1Eo, K2Eo, KNout);

    // opening node
    mm_launch(N, 0,   k1n, xn_in, 32, N, 128, nullptr, 0.0, acc+0, t, 0);
    mm_launch(N, 384, k2n, t, 128, N, 128, acc+0, 1.0/(128.0*N), nullptr, xnR, 3);

    // opening edge
    mm_launch(E, 128, k1e, xe_in, 32, E, 128, nullptr, 0.0, acc+2, t, 3);
    hmma_launch(E, 128, 128, 128, 128, bhOE, blOE, t, acc+2, 1.0/(128.0*E), nullptr,
                xe, 0, nullptr, 0, nullptr, nullptr);

    for (int l = 0; l < 4; l++) {
        double* accE = acc + 4 + 4*l;
        double* accN = acc + 6 + 4*l;
        // yAT[n][256] = wEa @ xn (two-pass)
        hmma2_launch(N, 384, bhEa + (size_t)l*256*128, blEa + (size_t)l*256*128, xnR,
                     nullptr, nullptr, nullptr, yAT);
        // edge mm1': t[e][256] = gather(yAT,iInd) + wEb @ xe (+stats accE)
        hmma2_launch(E, 128, bhE1 + (size_t)l*256*128, blE1 + (size_t)l*256*128, xe,
                     yAT, iInd, accE, t);
        zeroS<<<(N*64+255)/256, 256>>>(sN, N);
        // edge mm2: xe += 0.1*(KE2 @ relu(norm t)); scatter into sN rows
        hmma_launch(E, 128, 256, 256, 128, bhE2 + (size_t)l*128*256, blE2 + (size_t)l*128*256, t,
                    accE, 1.0/(256.0*E), nullptr, xe, 2, sN, 384, iInd, jInd);
        // node mm1: t[n][256] = N1 @ sN rows (K=384) (+stats accN)
        hmma_launch(N, 256, 384, 384, 256, bhN1 + (size_t)l*256*384, blN1 + (size_t)l*256*384, sN,
                    nullptr, 0.0, accN, t, 0, nullptr, 0, nullptr, nullptr);
        // node mm2: xn += 0.1*(N2 @ relu(norm t))
        hmma_launch(N, 128, 256, 256, 384, bhN2 + (size_t)l*128*256, blN2 + (size_t)l*128*256, t,
                    accN, 1.0/(256.0*N), nullptr, xnR, 1, nullptr, 0, nullptr, nullptr);
    }
    hmma_launch(N, 128, 128, 384, 128, bhKO, blKO, xnR,
                nullptr, 0.0, nullptr, yAT, 0, nullptr, 0, nullptr, nullptr);
    {
        dim3 tg((N+31)/32, 2), tb(32, 8);
        transposeNC<<<tg, tb>>>(yAT, out, N, 128, 64);
    }
    {
        dim3 tg((E+31)/32, 4), tb(32, 8);
        transposeNC<<<tg, tb>>>(xe, xe_out, E, 128, 128);
    }
}

// round 17
// speedup vs baseline: 1.5817x; 1.5817x over previous
#include <cuda_runtime.h>
#include <cuda_bf16.h>
#include <stdint.h>
#include <math.h>
#define NMAX 50000
#define EMAX 500000
typedef unsigned long long ull;
typedef unsigned int u32;
#define H2SM 104448   // hmma2: 4-chunk X (81920) + B (20480) + red pad

__device__ float g_t [(size_t)256*EMAX];
__device__ float g_xe[(size_t)128*EMAX];
__device__ float g_sN[(size_t)384*NMAX];
__device__ float g_yAT[(size_t)256*NMAX];
__device__ float g_k1n[32*128];
__device__ float g_k2n[128*128];
__device__ float g_k1e[32*128];
__device__ __nv_bfloat16 g_bhN1[4*256*384], g_blN1[4*256*384];
__device__ __nv_bfloat16 g_bhN2[4*128*256], g_blN2[4*128*256];
__device__ __nv_bfloat16 g_bhEa[4*256*128], g_blEa[4*256*128];
__device__ __nv_bfloat16 g_bhE1[4*256*128], g_blE1[4*256*128];
__device__ __nv_bfloat16 g_bhE2[4*128*256], g_blE2[4*128*256];
__device__ __nv_bfloat16 g_bhOE[128*128],   g_blOE[128*128];
__device__ __nv_bfloat16 g_bhKO[128*128],   g_blKO[128*128];
__device__ double g_acc[20];

__device__ __forceinline__ ull dup2(float v){ ull r; asm("mov.b64 %0,{%1,%1};":"=l"(r):"f"(v)); return r; }
__device__ __forceinline__ void ffma2(ull&d, ull a, ull b){ asm("fma.rn.f32x2 %0,%1,%2,%0;":"+l"(d):"l"(a),"l"(b)); }
__device__ __forceinline__ float2 f2of(ull u){ union{ull u; float2 f;} c; c.u=u; return c.f; }
__device__ __forceinline__ u32 smem_u32(const void*p){ u32 a; asm("{.reg .u64 t; cvta.to.shared.u64 t,%1; cvt.u32.u64 %0,t;}":"=r"(a):"l"(p)); return a; }
#define LDM4(r,a) asm volatile("ldmatrix.sync.aligned.m8n8.x4.shared.b16 {%0,%1,%2,%3},[%4];" \
    :"=r"((r)[0]),"=r"((r)[1]),"=r"((r)[2]),"=r"((r)[3]):"r"(a))
#define MMA(dd,a,b0,b1) asm volatile("mma.sync.aligned.m16n8k16.row.col.f32.bf16.bf16.f32 " \
    "{%0,%1,%2,%3},{%4,%5,%6,%7},{%8,%9},{%0,%1,%2,%3};" \
    :"+f"((dd)[0]),"+f"((dd)[1]),"+f"((dd)[2]),"+f"((dd)[3]) \
    :"r"((a)[0]),"r"((a)[1]),"r"((a)[2]),"r"((a)[3]),"r"(b0),"r"(b1))
#define REDV2(p,x0,x1) asm volatile("red.global.add.v2.f32 [%0], {%1, %2};" :: "l"(p), "f"(x0), "f"(x1) : "memory")

__device__ __forceinline__ void bsplit(float w, __nv_bfloat16& h, __nv_bfloat16& l){
    h = __float2bfloat16(w); l = __float2bfloat16(w - __bfloat162float(h));
}
__device__ __forceinline__ void bsplit8(const float* xv, uint4& uh, uint4& ul){
    __nv_bfloat162 h[4], l[4];
    #pragma unroll
    for (int p = 0; p < 4; p++) {
        float2 x2 = make_float2(xv[2*p], xv[2*p+1]);
        h[p] = __float22bfloat162_rn(x2);
        float2 hf = __bfloat1622float2(h[p]);
        l[p] = __float22bfloat162_rn(make_float2(x2.x - hf.x, x2.y - hf.y));
    }
    uh = *(uint4*)h; ul = *(uint4*)l;
}

__global__ void prep_kernelA(const float* __restrict__ KE1, const float* __restrict__ KN1,
                             const float* __restrict__ KE2, const float* __restrict__ KN2)
{
    int idx = blockIdx.x*blockDim.x + threadIdx.x;
    if (idx >= 4*256*384) return;
    int l = idx / (256*384), r = idx % (256*384);
    int o = r / 384, k = r % 384;
    {
        const float* n = KN1 + ((size_t)(l*256 + o))*384;
        int kk = k & 127, reg = k >> 7;
        float a = n[kk], b = n[128+kk];
        float w = (reg == 0) ? 0.5f*a + b : ((reg == 1) ? 0.5f*a - b : n[256+kk]);
        bsplit(w, g_bhN1[(size_t)(l*256+o)*384 + k], g_blN1[(size_t)(l*256+o)*384 + k]);
    }
    if (k < 128) {
        const float* e = KE1 + ((size_t)(l*256 + o))*384;
        int d = (l*256 + o)*128 + k;
        bsplit(e[k] + e[128+k], g_bhEa[d], g_blEa[d]);
        bsplit(e[256+k],        g_bhE1[d], g_blE1[d]);
    }
    if (o < 128 && k < 256) {
        int d = (l*128 + o)*256 + k;
        bsplit(KE2[(size_t)(l*128+o)*256 + k], g_bhE2[d], g_blE2[d]);
        bsplit(KN2[(size_t)(l*128+o)*256 + k], g_bhN2[d], g_blN2[d]);
    }
}
__global__ void prep_kernelB(const float* __restrict__ K1No, const float* __restrict__ K2No,
                             const float* __restrict__ K1Eo, const float* __restrict__ K2Eo,
                             const float* __restrict__ KNout)
{
    int idx = blockIdx.x*blockDim.x + threadIdx.x;
    if (idx >= 128*128) return;
    int o = idx&127, k = idx>>7;
    if (k < 32) { g_k1n[k*128+o] = K1No[o*32+k]; g_k1e[k*128+o] = K1Eo[o*32+k]; }
    g_k2n[k*128+o] = K2No[o*128+k];
    bsplit(K2Eo[o*128+k], g_bhOE[o*128+k], g_blOE[o*128+k]);
    bsplit((o < 64) ? KNout[o*128+k] : 0.f, g_bhKO[o*128+k], g_blKO[o*128+k]);
}

__global__ void zeroS(float* s, int N)
{
    int i = blockIdx.x*blockDim.x + threadIdx.x;
    if (i >= N*64) return;
    int n = i >> 6, c = (i & 63)*4;
    *(float4*)(s + (size_t)n*384 + c) = make_float4(0.f,0.f,0.f,0.f);
}

__global__ void transposeNC(const float* __restrict__ src, float* __restrict__ dst,
                            int M, int ldS, int rows)
{
    __shared__ float tl[32][33];
    int m0 = blockIdx.x*32, c0 = blockIdx.y*32;
    int tx = threadIdx.x, ty = threadIdx.y;
    #pragma unroll
    for (int i = 0; i < 32; i += 8) {
        int m = m0 + ty + i;
        tl[ty+i][tx] = (m < M) ? src[(size_t)m*ldS + c0 + tx] : 0.f;
    }
    __syncthreads();
    #pragma unroll
    for (int i = 0; i < 32; i += 8) {
        int m = m0 + tx, c = c0 + ty + i;
        if (m < M && c < rows) dst[(size_t)c*M + m] = tl[tx][ty+i];
    }
}

// ---------- generic HMMA GEMM (round-15 proven best; 256 threads) ----------
__global__ void __launch_bounds__(256, 2)
hmma_kernel(int E, int K, int ldX, int ldY,
            const __nv_bfloat16* __restrict__ Whi, const __nv_bfloat16* __restrict__ Wlo,
            const float* __restrict__ X,
            const float* __restrict__ gInit, const int* __restrict__ g0,
            const double* __restrict__ normAcc, double cntInv, double* __restrict__ statAcc,
            float* __restrict__ Y, int epi,
            float* __restrict__ sc, int ldS,
            const int* __restrict__ iI, const int* __restrict__ jI)
{
    __shared__ __align__(16) char smem[43008];
    const int A_H = 0, A_L = 10240, B_H = 20480, B_L = 30720;
    const u32 sb = smem_u32(smem);

    const int tid = threadIdx.x, warp = tid>>5, lane = tid&31;
    const int m0 = blockIdx.x*128;
    const int oB = blockIdx.y*128;
    const int wm = warp>>1, wn = warp&1;
    const int ce = tid & 127, cg = tid >> 7;
    const bool cev = (m0 + ce) < E;

    const __nv_bfloat16* WhB = Whi + (size_t)(oB + ce)*K;
    const __nv_bfloat16* WlB = Wlo + (size_t)(oB + ce)*K;

    float inv = 0.f, mi = 0.f;
    const bool dn = (normAcc != nullptr);
    if (dn) {
        double mu = normAcc[0]*cntInv, va = normAcc[1]*cntInv - mu*mu;
        inv = (float)rsqrt(va + 1e-5);
        mi  = (float)mu * inv;
    }

    float d[2][8][4];
    #pragma unroll
    for (int a = 0; a < 2; a++)
        #pragma unroll
        for (int b = 0; b < 8; b++)
            #pragma unroll
            for (int c = 0; c < 4; c++) d[a][b][c] = 0.f;

    const float* xrow = X + (size_t)(m0 + ce)*ldX + cg*16;

    const int C = K >> 5;
    for (int c = 0; c < C; c++) {
        const int k0 = c*32;
        __syncthreads();
        #pragma unroll
        for (int h = 0; h < 2; h++) {
            float xv[8];
            if (cev) {
                *(float4*)&xv[0] = *(const float4*)(xrow + k0 + h*8);
                *(float4*)&xv[4] = *(const float4*)(xrow + k0 + h*8 + 4);
            } else {
                #pragma unroll
                for (int i = 0; i < 8; i++) xv[i] = 0.f;
            }
            if (dn) {
                #pragma unroll
                for (int i = 0; i < 8; i++) xv[i] = fmaxf(fmaf(xv[i], inv, -mi), 0.f);
            }
            uint4 uh, ul;
            bsplit8(xv, uh, ul);
            int kof = cg*16 + h*8;
            *(uint4*)(smem + A_H + ce*80 + kof*2) = uh;
            *(uint4*)(smem + A_L + ce*80 + kof*2) = ul;
        }
        #pragma unroll
        for (int h = 0; h < 2; h++) {
            int kof = (cg + h*2)*8;
            *(uint4*)(smem + B_H + ce*80 + kof*2) = *(const uint4*)(WhB + k0 + kof);
            *(uint4*)(smem + B_L + ce*80 + kof*2) = *(const uint4*)(WlB + k0 + kof);
        }
        __syncthreads();
        #pragma unroll
        for (int kk = 0; kk < 32; kk += 16) {
            u32 ah[2][4], al[2][4];
            #pragma unroll
            for (int mt = 0; mt < 2; mt++) {
                u32 ra = sb + (u32)((wm*32 + mt*16 + (lane&15))*80 + (kk + ((lane>>4)<<3))*2);
                LDM4(ah[mt], A_H + ra);
                LDM4(al[mt], A_L + ra);
            }
            #pragma unroll
            for (int np = 0; np < 4; np++) {
                u32 rb = sb + (u32)((wn*64 + np*16 + (lane&7) + ((lane>>4)<<3))*80 + (kk + ((lane>>3)&1)*8)*2);
                u32 bh[4], bl[4];
                LDM4(bh, B_H + rb);
                LDM4(bl, B_L + rb);
                #pragma unroll
                for (int mt = 0; mt < 2; mt++) {
                    MMA(d[mt][np*2],   ah[mt], bh[0], bh[1]);
                    MMA(d[mt][np*2],   ah[mt], bl[0], bl[1]);
                    MMA(d[mt][np*2],   al[mt], bh[0], bh[1]);
                    MMA(d[mt][np*2+1], ah[mt], bh[2], bh[3]);
                    MMA(d[mt][np*2+1], ah[mt], bl[2], bl[3]);
                    MMA(d[mt][np*2+1], al[mt], bh[2], bh[3]);
                }
            }
        }
    }

    const int quad = lane>>2, tc = (lane&3)*2;
    float s = 0.f, q = 0.f;
    #pragma unroll
    for (int mt = 0; mt < 2; mt++) {
        #pragma unroll
        for (int hf = 0; hf < 2; hf++) {
            int e = m0 + wm*32 + mt*16 + quad + hf*8;
            if (e >= E) continue;
            const float* gp = nullptr;
            if (gInit) gp = gInit + (size_t)g0[e]*256;
            float *ip = nullptr, *jp = nullptr;
            if (epi == 2) {
                ip = sc + (size_t)iI[e]*ldS;
                jp = sc + (size_t)jI[e]*ldS + 128;
            }
            float* yrow = Y + (size_t)e*ldY + oB;
            #pragma unroll
            for (int nt = 0; nt < 8; nt++) {
                int oL = wn*64 + nt*8 + tc;
                float x0 = d[mt][nt][hf*2+0];
                float x1 = d[mt][nt][hf*2+1];
                if (gp) {
                    float2 g2 = *(const float2*)(gp + oB + oL);
                    x0 += g2.x; x1 += g2.y;
                }
                if (epi == 0) {
                    *(float2*)(yrow + oL) = make_float2(x0, x1);
                    s += x0 + x1; q += x0*x0 + x1*x1;
                } else {
                    float2 old = *(float2*)(yrow + oL);
                    old.x += 0.1f*x0; old.y += 0.1f*x1;
                    *(float2*)(yrow + oL) = old;
                    if (epi == 2) {
                        REDV2(ip + oL, x0, x1);
                        REDV2(jp + oL, x0, x1);
                    }
                }
            }
        }
    }
    if (statAcc) {
        float* rs = (float*)(smem + 40960); float* rq = rs + 256;
        __syncthreads();
        rs[tid] = s; rq[tid] = q;
        __syncthreads();
        for (int st = 128; st > 0; st >>= 1) {
            if (tid < st) { rs[tid] += rs[tid+st]; rq[tid] += rq[tid+st]; }
            __syncthreads();
        }
        if (tid == 0) { atomicAdd(statAcc, (double)rs[0]); atomicAdd(statAcc+1, (double)rq[0]); }
    }
}

// ---------- two-pass HMMA for K=128, O=256 (X staged once), float2 gather ----------
__global__ void __launch_bounds__(256, 2)
hmma2_kernel(int E, int ldX,
             const __nv_bfloat16* __restrict__ Whi, const __nv_bfloat16* __restrict__ Wlo,
             const float* __restrict__ X,
             const float* __restrict__ gInit, const int* __restrict__ g0,
             double* __restrict__ statAcc,
             float* __restrict__ Y)
{
    extern __shared__ __align__(16) char dsm[];
    const int B_H = 81920, B_L = 92160;
    const u32 sb = smem_u32(dsm);

    const int tid = threadIdx.x, warp = tid>>5, lane = tid&31;
    const int m0 = blockIdx.x*128;
    const int wm = warp>>1, wn = warp&1;
    const int ce = tid & 127, cg = tid >> 7;
    const bool cev = (m0 + ce) < E;

    const float* xrow = X + (size_t)(m0 + ce)*ldX + cg*16;

    #pragma unroll
    for (int c = 0; c < 4; c++) {
        const int k0 = c*32;
        char* ab = dsm + c*20480;
        #pragma unroll
        for (int h = 0; h < 2; h++) {
            float xv[8];
            if (cev) {
                *(float4*)&xv[0] = *(const float4*)(xrow + k0 + h*8);
                *(float4*)&xv[4] = *(const float4*)(xrow + k0 + h*8 + 4);
            } else {
                #pragma unroll
                for (int i = 0; i < 8; i++) xv[i] = 0.f;
            }
            uint4 uh, ul;
            bsplit8(xv, uh, ul);
            int kof = cg*16 + h*8;
            *(uint4*)(ab +         ce*80 + kof*2) = uh;
            *(uint4*)(ab + 10240 + ce*80 + kof*2) = ul;
        }
    }

    const int quad = lane>>2, tc = (lane&3)*2;
    float s = 0.f, q = 0.f;

    for (int oh = 0; oh < 2; oh++) {
        const int oB = oh*128;
        const __nv_bfloat16* WhB = Whi + (size_t)(oB + ce)*128;
        const __nv_bfloat16* WlB = Wlo + (size_t)(oB + ce)*128;

        float d[2][8][4];
        #pragma unroll
        for (int a = 0; a < 2; a++)
            #pragma unroll
            for (int b = 0; b < 8; b++)
                #pragma unroll
                for (int c = 0; c < 4; c++) d[a][b][c] = 0.f;

        for (int c = 0; c < 4; c++) {
            const int k0 = c*32;
            __syncthreads();
            #pragma unroll
            for (int h = 0; h < 2; h++) {
                int kof = (cg + h*2)*8;
                *(uint4*)(dsm + B_H + ce*80 + kof*2) = *(const uint4*)(WhB + k0 + kof);
                *(uint4*)(dsm + B_L + ce*80 + kof*2) = *(const uint4*)(WlB + k0 + kof);
            }
            __syncthreads();
            const u32 abs0 = sb + (u32)(c*20480);
            #pragma unroll
            for (int kk = 0; kk < 32; kk += 16) {
                u32 ah[2][4], al[2][4];
                #pragma unroll
                for (int mt = 0; mt < 2; mt++) {
                    u32 ra = (u32)((wm*32 + mt*16 + (lane&15))*80 + (kk + ((lane>>4)<<3))*2);
                    LDM4(ah[mt], abs0 + ra);
                    LDM4(al[mt], abs0 + 10240 + ra);
                }
                #pragma unroll
                for (int np = 0; np < 4; np++) {
                    u32 rb = sb + (u32)((wn*64 + np*16 + (lane&7) + ((lane>>4)<<3))*80 + (kk + ((lane>>3)&1)*8)*2);
                    u32 bh[4], bl[4];
                    LDM4(bh, B_H + rb);
                    LDM4(bl, B_L + rb);
                    #pragma unroll
                    for (int mt = 0; mt < 2; mt++) {
                        MMA(d[mt][np*2],   ah[mt], bh[0], bh[1]);
                        MMA(d[mt][np*2],   ah[mt], bl[0], bl[1]);
                        MMA(d[mt][np*2],   al[mt], bh[0], bh[1]);
                        MMA(d[mt][np*2+1], ah[mt], bh[2], bh[3]);
                        MMA(d[mt][np*2+1], ah[mt], bl[2], bl[3]);
                        MMA(d[mt][np*2+1], al[mt], bh[2], bh[3]);
                    }
                }
            }
        }

        #pragma unroll
        for (int mt = 0; mt < 2; mt++) {
            #pragma unroll
            for (int hf = 0; hf < 2; hf++) {
                int e = m0 + wm*32 + mt*16 + quad + hf*8;
                if (e >= E) continue;
                const float* gp = nullptr;
                if (gInit) gp = gInit + (size_t)g0[e]*256 + oB;
                float* yrow = Y + (size_t)e*256 + oB;
                #pragma unroll
                for (int nt = 0; nt < 8; nt++) {
                    int oL = wn*64 + nt*8 + tc;
                    float x0 = d[mt][nt][hf*2+0];
                    float x1 = d[mt][nt][hf*2+1];
                    if (gp) {
                        float2 g2 = *(const float2*)(gp + oL);
                        x0 += g2.x; x1 += g2.y;
                    }
                    *(float2*)(yrow + oL) = make_float2(x0, x1);
                    s += x0 + x1; q += x0*x0 + x1*x1;
                }
            }
        }
    }

    if (statAcc) {
        float* rs = (float*)(dsm + 102400); float* rq = rs + 256;
        __syncthreads();
        rs[tid] = s; rq[tid] = q;
        __syncthreads();
        for (int st = 128; st > 0; st >>= 1) {
            if (tid < st) { rs[tid] += rs[tid+st]; rq[tid] += rq[tid+st]; }
            __syncthreads();
        }
        if (tid == 0) { atomicAdd(statAcc, (double)rs[0]); atomicAdd(statAcc+1, (double)rq[0]); }
    }
}

// ---------- SIMT f32x2 GEMM (opening GEMMs only) ----------
__global__ void __launch_bounds__(256, 2)
mm4_kernel(int M, int Oact, int ldY3,
           const float* __restrict__ W0, const float* __restrict__ X0, int K0, int ld0, int ldW0,
           const double* __restrict__ normAcc, double cntInv, double* __restrict__ statAcc,
           float* __restrict__ Y, int epi)
{
    __shared__ __align__(16) ull   Wd[2][8][132];
    __shared__ __align__(16) float Xs[2][8][132];
    const int tid = threadIdx.x, m0 = blockIdx.x*128, wb = blockIdx.y*128;
    const int lane = tid&31, warp = tid>>5;
    const int rbase = (warp>>2)*64 + (lane>>2)*4;
    const int cbase = (warp&3)*32 + (lane&3)*4;
    const int kkS = tid>>5, mfS = (tid&31)*4;

    float mean = 0.f, inv = 0.f;
    const bool dn = (normAcc != nullptr);
    if (dn) {
        double mu = normAcc[0]*cntInv, va = normAcc[1]*cntInv - mu*mu;
        mean = (float)mu; inv = (float)rsqrt(va + 1e-5);
    }
    ull acc[8][4];
    #pragma unroll
    for (int r = 0; r < 8; r++) { acc[r][0]=acc[r][1]=acc[r][2]=acc[r][3]=0ull; }

    const int totT = K0 >> 3;
    auto ldg = [&](int t, float4& wv, float4& xv) {
        int k0 = t*8;
        wv = *(const float4*)(W0 + (size_t)(k0+kkS)*ldW0 + wb + mfS);
        int m = m0 + mfS;
        if (m < M) {
            float4 v = *(const float4*)(X0 + (size_t)(k0+kkS)*ld0 + m);
            if (dn) {
                v.x = fmaxf((v.x-mean)*inv, 0.f); v.y = fmaxf((v.y-mean)*inv, 0.f);
                v.z = fmaxf((v.z-mean)*inv, 0.f); v.w = fmaxf((v.w-mean)*inv, 0.f);
            }
            xv = v;
        } else xv = make_float4(0.f,0.f,0.f,0.f);
    };
    auto sts = [&](int b, const float4& wv, const float4& xv) {
        ull* wr = &Wd[b][kkS][mfS];
        wr[0]=dup2(wv.x); wr[1]=dup2(wv.y); wr[2]=dup2(wv.z); wr[3]=dup2(wv.w);
        *(float4*)&Xs[b][kkS][mfS] = xv;
    };
    { float4 wv, xv; ldg(0, wv, xv); sts(0, wv, xv); }
    __syncthreads();
    float4 wpv, xpv;
    for (int t = 0; t < totT; t++) {
        const int cur = t&1; const bool more = (t+1 < totT);
        if (more) ldg(t+1, wpv, xpv);
        #pragma unroll
        for (int kk = 0; kk < 8; kk++) {
            ulonglong2 w01 = *(const ulonglong2*)&Wd[cur][kk][rbase];
            ulonglong2 w23 = *(const ulonglong2*)&Wd[cur][kk][rbase+2];
            ulonglong2 w45 = *(const ulonglong2*)&Wd[cur][kk][rbase+32];
            ulonglong2 w67 = *(const ulonglong2*)&Wd[cur][kk][rbase+34];
            ulonglong2 xa = *(const ulonglong2*)&Xs[cur][kk][cbase];
            ulonglong2 xb = *(const ulonglong2*)&Xs[cur][kk][cbase+16];
            ffma2(acc[0][0],w01.x,xa.x); ffma2(acc[0][1],w01.x,xa.y); ffma2(acc[0][2],w01.x,xb.x); ffma2(acc[0][3],w01.x,xb.y);
            ffma2(acc[1][0],w01.y,xa.x); ffma2(acc[1][1],w01.y,xa.y); ffma2(acc[1][2],w01.y,xb.x); ffma2(acc[1][3],w01.y,xb.y);
            ffma2(acc[2][0],w23.x,xa.x); ffma2(acc[2][1],w23.x,xa.y); ffma2(acc[2][2],w23.x,xb.x); ffma2(acc[2][3],w23.x,xb.y);
            ffma2(acc[3][0],w23.y,xa.x); ffma2(acc[3][1],w23.y,xa.y); ffma2(acc[3][2],w23.y,xb.x); ffma2(acc[3][3],w23.y,xb.y);
            ffma2(acc[4][0],w45.x,xa.x); ffma2(acc[4][1],w45.x,xa.y); ffma2(acc[4][2],w45.x,xb.x); ffma2(acc[4][3],w45.x,xb.y);
            ffma2(acc[5][0],w45.y,xa.x); ffma2(acc[5][1],w45.y,xa.y); ffma2(acc[5][2],w45.y,xb.x); ffma2(acc[5][3],w45.y,xb.y);
            ffma2(acc[6][0],w67.x,xa.x); ffma2(acc[6][1],w67.x,xa.y); ffma2(acc[6][2],w67.x,xb.x); ffma2(acc[6][3],w67.x,xb.y);
            ffma2(acc[7][0],w67.y,xa.x); ffma2(acc[7][1],w67.y,xa.y); ffma2(acc[7][2],w67.y,xb.x); ffma2(acc[7][3],w67.y,xb.y);
        }
        if (more) sts(cur^1, wpv, xpv);
        __syncthreads();
    }
    if (statAcc) {
        float s = 0.f, q = 0.f;
        #pragma unroll
        for (int r = 0; r < 8; r++)
            #pragma unroll
            for (int cg = 0; cg < 2; cg++)
                if (m0 + cbase + cg*16 < M) {
                    float2 a = f2of(acc[r][cg*2]), b = f2of(acc[r][cg*2+1]);
                    s += a.x+a.y+b.x+b.y; q += a.x*a.x+a.y*a.y+b.x*b.x+b.y*b.y;
                }
        __syncthreads();
        float* rs = (float*)Wd; float* rq = rs + 256;
        rs[tid] = s; rq[tid] = q;
        __syncthreads();
        for (int st = 128; st > 0; st >>= 1) {
            if (tid < st) { rs[tid] += rs[tid+st]; rq[tid] += rq[tid+st]; }
            __syncthreads();
        }
        if (tid == 0) { atomicAdd(statAcc,(double)rs[0]); atomicAdd(statAcc+1,(double)rq[0]); }
    }
    if (epi == 3) {
        #pragma unroll
        for (int j = 0; j < 4; j++)
            #pragma unroll
            for (int h = 0; h < 2; h++) {
                int c = m0 + cbase + (j>>1)*16 + (j&1)*2 + h;
                if (c >= M) continue;
                float4 v0, v1;
                if (h == 0) {
                    v0 = make_float4(f2of(acc[0][j]).x, f2of(acc[1][j]).x, f2of(acc[2][j]).x, f2of(acc[3][j]).x);
                    v1 = make_float4(f2of(acc[4][j]).x, f2of(acc[5][j]).x, f2of(acc[6][j]).x, f2of(acc[7][j]).x);
                } else {
                    v0 = make_float4(f2of(acc[0][j]).y, f2of(acc[1][j]).y, f2of(acc[2][j]).y, f2of(acc[3][j]).y);
                    v1 = make_float4(f2of(acc[4][j]).y, f2of(acc[5][j]).y, f2of(acc[6][j]).y, f2of(acc[7][j]).y);
                }
                float* dst = Y + (size_t)c*ldY3 + wb + rbase;
                *(float4*)dst = v0; *(float4*)(dst+32) = v1;
            }
        return;
    }
    #pragma unroll
    for (int r = 0; r < 8; r++) {
        int o = wb + ((r < 4) ? (rbase + r) : (rbase + 28 + r));
        if (o >= Oact) continue;
        #pragma unroll
        for (int cg = 0; cg < 2; cg++) {
            int c = m0 + cbase + cg*16;
            if (c >= M) continue;
            float2 p0 = f2of(acc[r][cg*2]), p1 = f2of(acc[r][cg*2+1]);
            *(float4*)(Y + (size_t)o*M + c) = make_float4(p0.x, p0.y, p1.x, p1.y);
        }
    }
}

static inline void mm_launch(int M, int ldY3,
    const float* W0, const float* X0, int K0, int ld0, int ldW0,
    const double* nA, double ci, double* sA, float* Y, int epi)
{
    dim3 g((M+127)/128, 1);
    mm4_kernel<<<g, 256>>>(M, 128, ldY3, W0, X0, K0, ld0, ldW0, nA, ci, sA, Y, epi);
}
static inline void hmma_launch(int M, int O, int K, int ldX, int ldY,
    const __nv_bfloat16* Wh, const __nv_bfloat16* Wl, const float* X,
    const float* gI, const int* g0, const double* nA, double ci, double* sA,
    float* Y, int epi, float* sc, int ldS, const int* iI, const int* jI)
{
    dim3 g((M+127)/128, O/128);
    hmma_kernel<<<g, 256>>>(M, K, ldX, ldY, Wh, Wl, X, gI, g0, nA, ci, sA, Y, epi, sc, ldS, iI, jI);
}
static inline void hmma2_launch(int M, int ldX,
    const __nv_bfloat16* Wh, const __nv_bfloat16* Wl, const float* X,
    const float* gI, const int* g0, double* sA, float* Y)
{
    hmma2_kernel<<<(M+127)/128, 256, H2SM>>>(M, ldX, Wh, Wl, X, gI, g0, sA, Y);
}

extern "C" void kernel_launch(void* const* d_in, const int* in_sizes, int n_in,
                              void* d_out, int out_size)
{
    if (n_in < 13) return;
    const float* xn_in = (const float*)d_in[0];
    const float* xe_in = (const float*)d_in[1];
    const int* iInd = (const int*)d_in[2];
    const int* jInd = (const int*)d_in[3];
    const float* K1No = (const float*)d_in[4];
    const float* K2No = (const float*)d_in[5];
    const float* K1Eo = (const float*)d_in[6];
    const float* K2Eo = (const float*)d_in[7];
    const float* KNout= (const float*)d_in[8];
    const float* KE1  = (const float*)d_in[9];
    const float* KE2  = (const float*)d_in[10];
    const float* KN1  = (const float*)d_in[11];
    const float* KN2  = (const float*)d_in[12];
    int N = in_sizes[0]/32, E = in_sizes[1]/32;

    cudaFuncSetAttribute(hmma2_kernel, cudaFuncAttributeMaxDynamicSharedMemorySize, H2SM);

    float *t,*xe,*sN,*yAT,*k1n,*k2n,*k1e;
    __nv_bfloat16 *bhN1,*blN1,*bhN2,*blN2,*bhEa,*blEa,*bhE1,*blE1,*bhE2,*blE2,*bhOE,*blOE,*bhKO,*blKO;
    double* acc;
    cudaGetSymbolAddress((void**)&t,g_t);     cudaGetSymbolAddress((void**)&xe,g_xe);
    cudaGetSymbolAddress((void**)&sN,g_sN);   cudaGetSymbolAddress((void**)&yAT,g_yAT);
    cudaGetSymbolAddress((void**)&k1n,g_k1n); cudaGetSymbolAddress((void**)&k2n,g_k2n);
    cudaGetSymbolAddress((void**)&k1e,g_k1e);
    cudaGetSymbolAddress((void**)&bhN1,g_bhN1); cudaGetSymbolAddress((void**)&blN1,g_blN1);
    cudaGetSymbolAddress((void**)&bhN2,g_bhN2); cudaGetSymbolAddress((void**)&blN2,g_blN2);
    cudaGetSymbolAddress((void**)&bhEa,g_bhEa); cudaGetSymbolAddress((void**)&blEa,g_blEa);
    cudaGetSymbolAddress((void**)&bhE1,g_bhE1); cudaGetSymbolAddress((void**)&blE1,g_blE1);
    cudaGetSymbolAddress((void**)&bhE2,g_bhE2); cudaGetSymbolAddress((void**)&blE2,g_blE2);
    cudaGetSymbolAddress((void**)&bhOE,g_bhOE); cudaGetSymbolAddress((void**)&blOE,g_blOE);
    cudaGetSymbolAddress((void**)&bhKO,g_bhKO); cudaGetSymbolAddress((void**)&blKO,g_blKO);
    cudaGetSymbolAddress((void**)&acc,g_acc);

    float* out = (float*)d_out;
    float* xe_out = out + (size_t)64*N;
    float* xnR = sN + 256;

    cudaMemsetAsync(acc, 0, 20*sizeof(double), 0);
    prep_kernelA<<<(4*256*384+255)/256, 256>>>(KE1, KN1, KE2, KN2);
    prep_kernelB<<<(128*128+255)/256, 256>>>(K1No, K2No, K1Eo, K2Eo, KNout);

    // opening node
    mm_launch(N, 0,   k1n, xn_in, 32, N, 128, nullptr, 0.0, acc+0, t, 0);
    mm_launch(N, 384, k2n, t, 128, N, 128, acc+0, 1.0/(128.0*N), nullptr, xnR, 3);

    // opening edge
    mm_launch(E, 128, k1e, xe_in, 32, E, 128, nullptr, 0.0, acc+2, t, 3);
    hmma_launch(E, 128, 128, 128, 128, bhOE, blOE, t, nullptr, nullptr, acc+2, 1.0/(128.0*E), nullptr,
                xe, 0, nullptr, 0, nullptr, nullptr);

    for (int l = 0; l < 4; l++) {
        double* accE = acc + 4 + 4*l;
        double* accN = acc + 6 + 4*l;
        // yAT[n][256] = wEa @ xn (two-pass)
        hmma2_launch(N, 384, bhEa + (size_t)l*256*128, blEa + (size_t)l*256*128, xnR,
                     nullptr, nullptr, nullptr, yAT);
        // edge mm1': t[e][256] = gather(yAT,iInd) + wEb @ xe (+stats accE)
        hmma2_launch(E, 128, bhE1 + (size_t)l*256*128, blE1 + (size_t)l*256*128, xe,
                     yAT, iInd, accE, t);
        zeroS<<<(N*64+255)/256, 256>>>(sN, N);
        // edge mm2: xe += 0.1*(KE2 @ relu(norm t)); scatter into sN rows
        hmma_launch(E, 128, 256, 256, 128, bhE2 + (size_t)l*128*256, blE2 + (size_t)l*128*256, t,
                    nullptr, nullptr, accE, 1.0/(256.0*E), nullptr, xe, 2, sN, 384, iInd, jInd);
        // node mm1: t[n][256] = N1 @ sN rows (K=384) (+stats accN)
        hmma_launch(N, 256, 384, 384, 256, bhN1 + (size_t)l*256*384, blN1 + (size_t)l*256*384, sN,
                    nullptr, nullptr, nullptr, 0.0, accN, t, 0, nullptr, 0, nullptr, nullptr);
        // node mm2: xn += 0.1*(N2 @ relu(norm t))
        hmma_launch(N, 128, 256, 256, 384, bhN2 + (size_t)l*128*256, blN2 + (size_t)l*128*256, t,
                    nullptr, nullptr, accN, 1.0/(256.0*N), nullptr, xnR, 1, nullptr, 0, nullptr, nullptr);
    }
    hmma_launch(N, 128, 128, 384, 128, bhKO, blKO, xnR,
                nullptr, nullptr, nullptr, 0.0, nullptr, yAT, 0, nullptr, 0, nullptr, nullptr);
    {
        dim3 tg((N+31)/32, 2), tb(32, 8);
        transposeNC<<<tg, tb>>>(yAT, out, N, 128, 64);
    }
    {
        dim3 tg((E+31)/32, 4), tb(32, 8);
        transposeNC<<<tg, tb>>>(xe, xe_out, E, 128, 128);
    }
}